// round 13
// baseline (speedup 1.0000x reference)
#include <cuda_runtime.h>
#include <cuda_fp16.h>

// Problem constants (fixed by the dataset instance)
#define S_  6        // cameras
#define N_  16384    // queries
#define C_  128      // channels
#define H_  4        // heads
#define CH  32       // channels per head
#define P_  8        // sampling points
#define Z_  8        // z-anchors (point p uses anchor p)
#define HF  28
#define WF  50
#define M_  (HF*WF)  // 1400 value tokens
#define QPB 4        // queries per block (main kernel)
#define TPB 8        // tokens per block (vproj)
#define PQ  2        // queries per block (param kernel)

// ---------------- scratch (device globals; no allocation) ----------------
__device__ __half  g_vtmp [S_ * H_ * M_ * CH];      // projected values, fp16
__device__ __half2 g_vpair[S_ * H_ * M_ * CH];      // x-pairs: (v[m], v[m_next])
__device__ float   g_param[N_ * 96];                // per-query: 64 scaled offsets + 32 probs
__device__ __half2 g_woutp[64 * C_];                // Wout packed as k-pairs

// ---------------- f32x2 helpers ----------------
union F2U { float2 f; unsigned long long u; };
union H2I { __half2 h; int i; };

__device__ __forceinline__ unsigned long long pk2(float x, float y) {
    F2U u; u.f = make_float2(x, y); return u.u;
}
__device__ __forceinline__ float2 upk2(unsigned long long v) {
    F2U u; u.u = v; return u.f;
}
__device__ __forceinline__ void ffma2(unsigned long long& d,
                                      unsigned long long a, unsigned long long b) {
    asm("fma.rn.f32x2 %0, %1, %2, %0;" : "+l"(d) : "l"(a), "l"(b));
}

// ---------------------------------------------------------------------------
// K0: pack Wout into half2 k-pairs: g_woutp[k2*C + c] = (Wout[2k2][c], Wout[2k2+1][c])
// ---------------------------------------------------------------------------
__global__ void woutpack_kernel(const float* __restrict__ Wout) {
    const int idx = blockIdx.x * 256 + threadIdx.x;   // 0..8191
    const int k2 = idx >> 7, c = idx & 127;
    g_woutp[idx] = __floats2half2_rn(Wout[(2 * k2) * C_ + c],
                                     Wout[(2 * k2 + 1) * C_ + c]);
}

// ---------------------------------------------------------------------------
// K1: value projection -> fp16, 8 tokens per block, f32x2 math.
// ---------------------------------------------------------------------------
__global__ __launch_bounds__(128) void vproj_kernel(
    const float* __restrict__ value,   // (S, M, 1, C)
    const float* __restrict__ Wv,      // (C, C)
    const float* __restrict__ bv)      // (C,)
{
    const int sm0 = blockIdx.x * TPB;
    const int t   = threadIdx.x;
    __shared__ float vsI[C_][12];     // [c][token], padded
#pragma unroll
    for (int i = 0; i < TPB; i++)
        vsI[t][i] = value[(sm0 + i) * C_ + t];
    __syncthreads();

    unsigned long long acc[4];
    const float b = bv[t];
#pragma unroll
    for (int j = 0; j < 4; j++) acc[j] = pk2(b, b);

#pragma unroll 4
    for (int k = 0; k < C_; k++) {
        const float wv = Wv[k * C_ + t];
        const unsigned long long w = pk2(wv, wv);
        const unsigned long long* vr = (const unsigned long long*)&vsI[k][0];
        ffma2(acc[0], vr[0], w);
        ffma2(acc[1], vr[1], w);
        ffma2(acc[2], vr[2], w);
        ffma2(acc[3], vr[3], w);
    }

    const int h = t >> 5, ch = t & 31;
#pragma unroll
    for (int j = 0; j < 4; j++) {
        const float2 v = upk2(acc[j]);
        {
            const int sm = sm0 + 2 * j;
            const int s = sm / M_, m = sm - s * M_;
            g_vtmp[((s * H_ + h) * M_ + m) * CH + ch] = __float2half(v.x);
        }
        {
            const int sm = sm0 + 2 * j + 1;
            const int s = sm / M_, m = sm - s * M_;
            g_vtmp[((s * H_ + h) * M_ + m) * CH + ch] = __float2half(v.y);
        }
    }
}

// ---------------------------------------------------------------------------
// K1b: build x-pairs: g_vpair[(sh,m,ch)] = (v[m], v[m+1 or m]) within the row.
// ---------------------------------------------------------------------------
__global__ void pairbuild_kernel() {
    const int idx = blockIdx.x * 256 + threadIdx.x;   // < S*H*M*CH
    const int ch = idx & (CH - 1);
    const int m  = (idx / CH) % M_;
    const int sh = idx / (M_ * CH);
    const int x  = m % WF;
    const int mnext = (x < WF - 1) ? m + 1 : m;
    g_vpair[idx] = __halves2half2(g_vtmp[(sh * M_ + m) * CH + ch],
                                  g_vtmp[(sh * M_ + mnext) * CH + ch]);
}

// ---------------------------------------------------------------------------
// K2 (rebuilt): sampling params. One 96-thread block per PQ=2 queries.
// Thread t = output column j (j<64: offsets via Wo; j>=64: attn via Wa).
// Both queries' q+pos packed as float2 in SMEM -> one LDS.64 feeds 2 FMAs.
// Warp 2 does the 8-point softmax for both queries via shuffles.
// ---------------------------------------------------------------------------
__global__ __launch_bounds__(96) void param_kernel(
    const float* __restrict__ query,
    const float* __restrict__ query_pos,
    const float* __restrict__ Wo,      // (C, 64)
    const float* __restrict__ bo,      // (64,)
    const float* __restrict__ Wa,      // (C, 32)
    const float* __restrict__ ba)      // (32,)
{
    const int n0 = blockIdx.x * PQ;
    const int t  = threadIdx.x;        // 0..95
    __shared__ float2 qsI[C_];         // {q0+pos0, q1+pos1}[c]

    {
        float* f = (float*)qsI;        // f[c*2 + qq]
        for (int i = t; i < PQ * C_; i += 96) {
            const int qq = i >> 7, c = i & 127;
            f[c * 2 + qq] = query[(n0 + qq) * C_ + c] + query_pos[(n0 + qq) * C_ + c];
        }
    }
    __syncthreads();

    // weight column pointer (warp-uniform branch: warps 0,1 -> Wo; warp 2 -> Wa)
    const bool isOff = (t < 64);
    const float* __restrict__ wp = isOff ? (Wo + t) : (Wa + (t - 64));
    const int stride = isOff ? 64 : 32;

    float acc0 = 0.0f, acc1 = 0.0f;
#pragma unroll 8
    for (int k = 0; k < C_; k++) {
        const float w = wp[k * stride];
        const float2 qv = qsI[k];
        acc0 = fmaf(qv.x, w, acc0);
        acc1 = fmaf(qv.y, w, acc1);
    }

    if (isOff) {
        const float b = bo[t];
        const float sc = (t & 1) ? (1.0f / HF) : (1.0f / WF);
        g_param[(n0 + 0) * 96 + t] = (acc0 + b) * sc;
        g_param[(n0 + 1) * 96 + t] = (acc1 + b) * sc;
    } else {
        // softmax over 8-point groups within warp 2, for both queries
        const float b = ba[t - 64];
        float l0 = acc0 + b, l1 = acc1 + b;
        float m0 = l0, m1 = l1;
#pragma unroll
        for (int d = 1; d < 8; d <<= 1) {
            m0 = fmaxf(m0, __shfl_xor_sync(0xffffffffu, m0, d));
            m1 = fmaxf(m1, __shfl_xor_sync(0xffffffffu, m1, d));
        }
        float e0 = expf(l0 - m0), e1 = expf(l1 - m1);
        float s0 = e0, s1 = e1;
#pragma unroll
        for (int d = 1; d < 8; d <<= 1) {
            s0 += __shfl_xor_sync(0xffffffffu, s0, d);
            s1 += __shfl_xor_sync(0xffffffffu, s1, d);
        }
        g_param[(n0 + 0) * 96 + t] = e0 / s0;
        g_param[(n0 + 1) * 96 + t] = e1 / s1;
    }
}

// ---------------------------------------------------------------------------
// K3: main — bilinear gather over x-pairs + fused output projection.
// ---------------------------------------------------------------------------
__global__ __launch_bounds__(128) void bevformer_main_kernel(
    const float* __restrict__ query,     // (1, N, C) for residual
    const float* __restrict__ ref,       // (S, 1, N, Z, 2)
    const int*   __restrict__ mask,      // (S, 1, N, Z) 4-byte words
    const float* __restrict__ bout,      // (C,)
    float*       __restrict__ out)       // (1, N, C)
{
    const int nb   = blockIdx.x * QPB;
    const int t    = threadIdx.x;
    const int warp = t >> 5, lane = t & 31;

    __shared__ int4  spar[QPB][S_][32];   // per (qi,s,head*8+p): {wt(h2), wb(h2), it, ib}
    __shared__ float sslX[64][8];         // [k2][(k&1)*4 + qi]
    __shared__ int   smaskA[QPB][S_];

    // ---- Phase C: warp = query qi; lane = head*8 + point ----
    {
        const int qi = warp;
        const int n  = nb + qi;
        const int p  = lane & 7;
        const float* pp = g_param + n * 96;
        const float aprob = pp[64 + lane];
        const float ox = pp[2 * lane], oy = pp[2 * lane + 1];

#pragma unroll
        for (int s = 0; s < S_; s++) {
            const float rx = ref[((s * N_ + n) * Z_ + p) * 2 + 0];
            const float ry = ref[((s * N_ + n) * Z_ + p) * 2 + 1];
            const float x = (rx + ox) * WF - 0.5f;
            const float y = (ry + oy) * HF - 0.5f;
            const float xf = floorf(x), yf = floorf(y);
            const float fx = x - xf,    fy = y - yf;
            const int   x0 = (int)xf,   y0 = (int)yf;

            // x-pair slot weights (pair base xp covers columns xp, xp+1)
            const int xp = min(max(x0, 0), WF - 2);
            float wa, wb;
            if (x0 >= 0 && x0 < WF - 1)      { wa = 1.0f - fx; wb = fx;   }
            else if (x0 == -1)               { wa = fx;        wb = 0.0f; }
            else if (x0 == WF - 1)           { wa = 0.0f;      wb = 1.0f - fx; }
            else                             { wa = 0.0f;      wb = 0.0f; }

            const float vy0 = (y0 >= 0     && y0 < HF)     ? 1.0f : 0.0f;
            const float vy1 = (y0 + 1 >= 0 && y0 + 1 < HF) ? 1.0f : 0.0f;
            const int yc0 = min(max(y0, 0), HF - 1);
            const int yc1 = min(max(y0 + 1, 0), HF - 1);
            const float wtop = aprob * (1.0f - fy) * vy0;
            const float wbot = aprob * fy * vy1;

            H2I u1; u1.h = __floats2half2_rn(wtop * wa, wtop * wb);
            H2I u2; u2.h = __floats2half2_rn(wbot * wa, wbot * wb);
            int4 pk;
            pk.x = u1.i;
            pk.y = u2.i;
            pk.z = (yc0 * WF + xp) * CH;
            pk.w = (yc1 * WF + xp) * CH;
            spar[qi][s][lane] = pk;

            const int word = (lane < Z_) ? mask[(s * N_ + n) * Z_ + lane] : 0;
            const int any = __any_sync(0xffffffffu, word != 0);
            if (lane == 0) smaskA[qi][s] = any;
        }
    }
    __syncthreads();

    // ---- Phase D: warp = head; gather pairs for 4 queries, 6 cams ----
    {
        const int h = warp, ch = lane;
        float slots[QPB] = {0.f, 0.f, 0.f, 0.f};
#pragma unroll
        for (int s = 0; s < S_; s++) {
            const __half2* __restrict__ vp =
                g_vpair + (size_t)((s * H_ + h) * M_) * CH + ch;
#pragma unroll
            for (int qi = 0; qi < QPB; qi++) {
                if (!smaskA[qi][s]) continue;
                float acc = 0.0f;
#pragma unroll
                for (int p = 0; p < P_; p++) {
                    const int4 pk = spar[qi][s][h * 8 + p];
                    H2I u1; u1.i = pk.x;
                    H2I u2; u2.i = pk.y;
                    const float2 wt = __half22float2(u1.h);
                    const float2 wb = __half22float2(u2.h);
                    const float2 tv = __half22float2(vp[pk.z]);
                    const float2 bv = __half22float2(vp[pk.w]);
                    acc = fmaf(wt.x, tv.x, acc);
                    acc = fmaf(wt.y, tv.y, acc);
                    acc = fmaf(wb.x, bv.x, acc);
                    acc = fmaf(wb.y, bv.y, acc);
                }
                slots[qi] += acc;
            }
        }
        const int c = h * 32 + ch;   // output channel 0..127
#pragma unroll
        for (int qi = 0; qi < QPB; qi++) {
            int cnt = 0;
#pragma unroll
            for (int s = 0; s < S_; s++) cnt += smaskA[qi][s];
            sslX[c >> 1][(c & 1) * 4 + qi] = slots[qi] / fmaxf((float)cnt, 1.0f);
        }
    }
    __syncthreads();

    // ---- Phase E: out = ssl @ Wout + bout + query (f32x2 over query pairs) ----
    {
        const float b = bout[t];
        unsigned long long o01 = pk2(b + query[(nb + 0) * C_ + t],
                                     b + query[(nb + 1) * C_ + t]);
        unsigned long long o23 = pk2(b + query[(nb + 2) * C_ + t],
                                     b + query[(nb + 3) * C_ + t]);
#pragma unroll 4
        for (int k2 = 0; k2 < 64; k2++) {
            const __half2 w2 = g_woutp[k2 * C_ + t];
            const float2 wf = __half22float2(w2);
            const unsigned long long w0 = pk2(wf.x, wf.x);
            const unsigned long long w1 = pk2(wf.y, wf.y);
            const unsigned long long* sx = (const unsigned long long*)&sslX[k2][0];
            ffma2(o01, sx[0], w0);
            ffma2(o23, sx[1], w0);
            ffma2(o01, sx[2], w1);
            ffma2(o23, sx[3], w1);
        }
        const float2 r01 = upk2(o01), r23 = upk2(o23);
        out[(nb + 0) * C_ + t] = r01.x;
        out[(nb + 1) * C_ + t] = r01.y;
        out[(nb + 2) * C_ + t] = r23.x;
        out[(nb + 3) * C_ + t] = r23.y;
    }
}

// ---------------------------------------------------------------------------
// Launch. Input order: query, query_pos, value, reference_points_cam,
// bev_mask, Wv, bv, Wo, bo, Wa, ba, Wout, bout, Hf, Wf
// ---------------------------------------------------------------------------
extern "C" void kernel_launch(void* const* d_in, const int* in_sizes, int n_in,
                              void* d_out, int out_size)
{
    const float* query     = (const float*)d_in[0];
    const float* query_pos = (const float*)d_in[1];
    const float* value     = (const float*)d_in[2];
    const float* refpts    = (const float*)d_in[3];
    const int*   bev_mask  = (const int*)  d_in[4];
    const float* Wv        = (const float*)d_in[5];
    const float* bv        = (const float*)d_in[6];
    const float* Wo        = (const float*)d_in[7];
    const float* bo        = (const float*)d_in[8];
    const float* Wa        = (const float*)d_in[9];
    const float* ba        = (const float*)d_in[10];
    const float* Wout      = (const float*)d_in[11];
    const float* bout      = (const float*)d_in[12];
    float* out = (float*)d_out;

    woutpack_kernel<<<(64 * C_) / 256, 256>>>(Wout);
    vproj_kernel<<<(S_ * M_) / TPB, 128>>>(value, Wv, bv);
    pairbuild_kernel<<<(S_ * H_ * M_ * CH) / 256, 256>>>();
    param_kernel<<<N_ / PQ, 96>>>(query, query_pos, Wo, bo, Wa, ba);
    bevformer_main_kernel<<<N_ / QPB, 128>>>(query, refpts, bev_mask, bout, out);
}

// round 14
// speedup vs baseline: 1.0019x; 1.0019x over previous
#include <cuda_runtime.h>
#include <cuda_fp16.h>

// Problem constants (fixed by the dataset instance)
#define S_  6        // cameras
#define N_  16384    // queries
#define C_  128      // channels
#define H_  4        // heads
#define CH  32       // channels per head
#define P_  8        // sampling points
#define Z_  8        // z-anchors (point p uses anchor p)
#define HF  28
#define WF  50
#define M_  (HF*WF)  // 1400 value tokens
#define QPB 4        // queries per block (main kernel)
#define TPB 8        // tokens per block (vproj)
#define PQ  2        // queries per block (param kernel)

// ---------------- scratch (device globals; no allocation) ----------------
__device__ __half  g_vtmp [S_ * H_ * M_ * CH];      // projected values, fp16
__device__ __half2 g_vpair[S_ * H_ * M_ * CH];      // x-pairs: (v[m], v[m_next])
__device__ float   g_param[N_ * 96];                // per-query: 64 scaled offsets + 32 probs
__device__ __half2 g_woutp[64 * C_];                // Wout packed as k-pairs

// ---------------- f32x2 helpers ----------------
union F2U { float2 f; unsigned long long u; };
union H2I { __half2 h; int i; };

__device__ __forceinline__ unsigned long long pk2(float x, float y) {
    F2U u; u.f = make_float2(x, y); return u.u;
}
__device__ __forceinline__ float2 upk2(unsigned long long v) {
    F2U u; u.u = v; return u.f;
}
__device__ __forceinline__ void ffma2(unsigned long long& d,
                                      unsigned long long a, unsigned long long b) {
    asm("fma.rn.f32x2 %0, %1, %2, %0;" : "+l"(d) : "l"(a), "l"(b));
}

// ---------------------------------------------------------------------------
// K0: pack Wout into half2 k-pairs: g_woutp[k2*C + c] = (Wout[2k2][c], Wout[2k2+1][c])
// ---------------------------------------------------------------------------
__global__ void woutpack_kernel(const float* __restrict__ Wout) {
    const int idx = blockIdx.x * 256 + threadIdx.x;   // 0..8191
    const int k2 = idx >> 7, c = idx & 127;
    g_woutp[idx] = __floats2half2_rn(Wout[(2 * k2) * C_ + c],
                                     Wout[(2 * k2 + 1) * C_ + c]);
}

// ---------------------------------------------------------------------------
// K1: value projection -> fp16, 8 tokens per block, f32x2 math.
// ---------------------------------------------------------------------------
__global__ __launch_bounds__(128) void vproj_kernel(
    const float* __restrict__ value,   // (S, M, 1, C)
    const float* __restrict__ Wv,      // (C, C)
    const float* __restrict__ bv)      // (C,)
{
    const int sm0 = blockIdx.x * TPB;
    const int t   = threadIdx.x;
    __shared__ float vsI[C_][12];     // [c][token], padded
#pragma unroll
    for (int i = 0; i < TPB; i++)
        vsI[t][i] = value[(sm0 + i) * C_ + t];
    __syncthreads();

    unsigned long long acc[4];
    const float b = bv[t];
#pragma unroll
    for (int j = 0; j < 4; j++) acc[j] = pk2(b, b);

#pragma unroll 4
    for (int k = 0; k < C_; k++) {
        const float wv = Wv[k * C_ + t];
        const unsigned long long w = pk2(wv, wv);
        const unsigned long long* vr = (const unsigned long long*)&vsI[k][0];
        ffma2(acc[0], vr[0], w);
        ffma2(acc[1], vr[1], w);
        ffma2(acc[2], vr[2], w);
        ffma2(acc[3], vr[3], w);
    }

    const int h = t >> 5, ch = t & 31;
#pragma unroll
    for (int j = 0; j < 4; j++) {
        const float2 v = upk2(acc[j]);
        {
            const int sm = sm0 + 2 * j;
            const int s = sm / M_, m = sm - s * M_;
            g_vtmp[((s * H_ + h) * M_ + m) * CH + ch] = __float2half(v.x);
        }
        {
            const int sm = sm0 + 2 * j + 1;
            const int s = sm / M_, m = sm - s * M_;
            g_vtmp[((s * H_ + h) * M_ + m) * CH + ch] = __float2half(v.y);
        }
    }
}

// ---------------------------------------------------------------------------
// K1b: build x-pairs: g_vpair[(sh,m,ch)] = (v[m], v[m+1 or m]) within the row.
// ---------------------------------------------------------------------------
__global__ void pairbuild_kernel() {
    const int idx = blockIdx.x * 256 + threadIdx.x;   // < S*H*M*CH
    const int ch = idx & (CH - 1);
    const int m  = (idx / CH) % M_;
    const int sh = idx / (M_ * CH);
    const int x  = m % WF;
    const int mnext = (x < WF - 1) ? m + 1 : m;
    g_vpair[idx] = __halves2half2(g_vtmp[(sh * M_ + m) * CH + ch],
                                  g_vtmp[(sh * M_ + mnext) * CH + ch]);
}

// ---------------------------------------------------------------------------
// K2 (rebuilt): sampling params. One 96-thread block per PQ=2 queries.
// Thread t = output column j (j<64: offsets via Wo; j>=64: attn via Wa).
// Both queries' q+pos packed as float2 in SMEM -> one LDS.64 feeds 2 FMAs.
// Warp 2 does the 8-point softmax for both queries via shuffles.
// ---------------------------------------------------------------------------
__global__ __launch_bounds__(96) void param_kernel(
    const float* __restrict__ query,
    const float* __restrict__ query_pos,
    const float* __restrict__ Wo,      // (C, 64)
    const float* __restrict__ bo,      // (64,)
    const float* __restrict__ Wa,      // (C, 32)
    const float* __restrict__ ba)      // (32,)
{
    const int n0 = blockIdx.x * PQ;
    const int t  = threadIdx.x;        // 0..95
    __shared__ float2 qsI[C_];         // {q0+pos0, q1+pos1}[c]

    {
        float* f = (float*)qsI;        // f[c*2 + qq]
        for (int i = t; i < PQ * C_; i += 96) {
            const int qq = i >> 7, c = i & 127;
            f[c * 2 + qq] = query[(n0 + qq) * C_ + c] + query_pos[(n0 + qq) * C_ + c];
        }
    }
    __syncthreads();

    // weight column pointer (warp-uniform branch: warps 0,1 -> Wo; warp 2 -> Wa)
    const bool isOff = (t < 64);
    const float* __restrict__ wp = isOff ? (Wo + t) : (Wa + (t - 64));
    const int stride = isOff ? 64 : 32;

    float acc0 = 0.0f, acc1 = 0.0f;
#pragma unroll 8
    for (int k = 0; k < C_; k++) {
        const float w = wp[k * stride];
        const float2 qv = qsI[k];
        acc0 = fmaf(qv.x, w, acc0);
        acc1 = fmaf(qv.y, w, acc1);
    }

    if (isOff) {
        const float b = bo[t];
        const float sc = (t & 1) ? (1.0f / HF) : (1.0f / WF);
        g_param[(n0 + 0) * 96 + t] = (acc0 + b) * sc;
        g_param[(n0 + 1) * 96 + t] = (acc1 + b) * sc;
    } else {
        // softmax over 8-point groups within warp 2, for both queries
        const float b = ba[t - 64];
        float l0 = acc0 + b, l1 = acc1 + b;
        float m0 = l0, m1 = l1;
#pragma unroll
        for (int d = 1; d < 8; d <<= 1) {
            m0 = fmaxf(m0, __shfl_xor_sync(0xffffffffu, m0, d));
            m1 = fmaxf(m1, __shfl_xor_sync(0xffffffffu, m1, d));
        }
        float e0 = expf(l0 - m0), e1 = expf(l1 - m1);
        float s0 = e0, s1 = e1;
#pragma unroll
        for (int d = 1; d < 8; d <<= 1) {
            s0 += __shfl_xor_sync(0xffffffffu, s0, d);
            s1 += __shfl_xor_sync(0xffffffffu, s1, d);
        }
        g_param[(n0 + 0) * 96 + t] = e0 / s0;
        g_param[(n0 + 1) * 96 + t] = e1 / s1;
    }
}

// ---------------------------------------------------------------------------
// K3: main — bilinear gather over x-pairs + fused output projection.
// ---------------------------------------------------------------------------
__global__ __launch_bounds__(128) void bevformer_main_kernel(
    const float* __restrict__ query,     // (1, N, C) for residual
    const float* __restrict__ ref,       // (S, 1, N, Z, 2)
    const int*   __restrict__ mask,      // (S, 1, N, Z) 4-byte words
    const float* __restrict__ bout,      // (C,)
    float*       __restrict__ out)       // (1, N, C)
{
    const int nb   = blockIdx.x * QPB;
    const int t    = threadIdx.x;
    const int warp = t >> 5, lane = t & 31;

    __shared__ int4  spar[QPB][S_][32];   // per (qi,s,head*8+p): {wt(h2), wb(h2), it, ib}
    __shared__ float sslX[64][8];         // [k2][(k&1)*4 + qi]
    __shared__ int   smaskA[QPB][S_];

    // ---- Phase C: warp = query qi; lane = head*8 + point ----
    {
        const int qi = warp;
        const int n  = nb + qi;
        const int p  = lane & 7;
        const float* pp = g_param + n * 96;
        const float aprob = pp[64 + lane];
        const float ox = pp[2 * lane], oy = pp[2 * lane + 1];

#pragma unroll
        for (int s = 0; s < S_; s++) {
            const float rx = ref[((s * N_ + n) * Z_ + p) * 2 + 0];
            const float ry = ref[((s * N_ + n) * Z_ + p) * 2 + 1];
            const float x = (rx + ox) * WF - 0.5f;
            const float y = (ry + oy) * HF - 0.5f;
            const float xf = floorf(x), yf = floorf(y);
            const float fx = x - xf,    fy = y - yf;
            const int   x0 = (int)xf,   y0 = (int)yf;

            // x-pair slot weights (pair base xp covers columns xp, xp+1)
            const int xp = min(max(x0, 0), WF - 2);
            float wa, wb;
            if (x0 >= 0 && x0 < WF - 1)      { wa = 1.0f - fx; wb = fx;   }
            else if (x0 == -1)               { wa = fx;        wb = 0.0f; }
            else if (x0 == WF - 1)           { wa = 0.0f;      wb = 1.0f - fx; }
            else                             { wa = 0.0f;      wb = 0.0f; }

            const float vy0 = (y0 >= 0     && y0 < HF)     ? 1.0f : 0.0f;
            const float vy1 = (y0 + 1 >= 0 && y0 + 1 < HF) ? 1.0f : 0.0f;
            const int yc0 = min(max(y0, 0), HF - 1);
            const int yc1 = min(max(y0 + 1, 0), HF - 1);
            const float wtop = aprob * (1.0f - fy) * vy0;
            const float wbot = aprob * fy * vy1;

            H2I u1; u1.h = __floats2half2_rn(wtop * wa, wtop * wb);
            H2I u2; u2.h = __floats2half2_rn(wbot * wa, wbot * wb);
            int4 pk;
            pk.x = u1.i;
            pk.y = u2.i;
            pk.z = (yc0 * WF + xp) * CH;
            pk.w = (yc1 * WF + xp) * CH;
            spar[qi][s][lane] = pk;

            const int word = (lane < Z_) ? mask[(s * N_ + n) * Z_ + lane] : 0;
            const int any = __any_sync(0xffffffffu, word != 0);
            if (lane == 0) smaskA[qi][s] = any;
        }
    }
    __syncthreads();

    // ---- Phase D: warp = head; gather pairs for 4 queries, 6 cams ----
    {
        const int h = warp, ch = lane;
        float slots[QPB] = {0.f, 0.f, 0.f, 0.f};
#pragma unroll
        for (int s = 0; s < S_; s++) {
            const __half2* __restrict__ vp =
                g_vpair + (size_t)((s * H_ + h) * M_) * CH + ch;
#pragma unroll
            for (int qi = 0; qi < QPB; qi++) {
                if (!smaskA[qi][s]) continue;
                float acc = 0.0f;
#pragma unroll
                for (int p = 0; p < P_; p++) {
                    const int4 pk = spar[qi][s][h * 8 + p];
                    H2I u1; u1.i = pk.x;
                    H2I u2; u2.i = pk.y;
                    const float2 wt = __half22float2(u1.h);
                    const float2 wb = __half22float2(u2.h);
                    const float2 tv = __half22float2(vp[pk.z]);
                    const float2 bv = __half22float2(vp[pk.w]);
                    acc = fmaf(wt.x, tv.x, acc);
                    acc = fmaf(wt.y, tv.y, acc);
                    acc = fmaf(wb.x, bv.x, acc);
                    acc = fmaf(wb.y, bv.y, acc);
                }
                slots[qi] += acc;
            }
        }
        const int c = h * 32 + ch;   // output channel 0..127
#pragma unroll
        for (int qi = 0; qi < QPB; qi++) {
            int cnt = 0;
#pragma unroll
            for (int s = 0; s < S_; s++) cnt += smaskA[qi][s];
            sslX[c >> 1][(c & 1) * 4 + qi] = slots[qi] / fmaxf((float)cnt, 1.0f);
        }
    }
    __syncthreads();

    // ---- Phase E: out = ssl @ Wout + bout + query (f32x2 over query pairs) ----
    {
        const float b = bout[t];
        unsigned long long o01 = pk2(b + query[(nb + 0) * C_ + t],
                                     b + query[(nb + 1) * C_ + t]);
        unsigned long long o23 = pk2(b + query[(nb + 2) * C_ + t],
                                     b + query[(nb + 3) * C_ + t]);
#pragma unroll 4
        for (int k2 = 0; k2 < 64; k2++) {
            const __half2 w2 = g_woutp[k2 * C_ + t];
            const float2 wf = __half22float2(w2);
            const unsigned long long w0 = pk2(wf.x, wf.x);
            const unsigned long long w1 = pk2(wf.y, wf.y);
            const unsigned long long* sx = (const unsigned long long*)&sslX[k2][0];
            ffma2(o01, sx[0], w0);
            ffma2(o23, sx[1], w0);
            ffma2(o01, sx[2], w1);
            ffma2(o23, sx[3], w1);
        }
        const float2 r01 = upk2(o01), r23 = upk2(o23);
        out[(nb + 0) * C_ + t] = r01.x;
        out[(nb + 1) * C_ + t] = r01.y;
        out[(nb + 2) * C_ + t] = r23.x;
        out[(nb + 3) * C_ + t] = r23.y;
    }
}

// ---------------------------------------------------------------------------
// Launch. Input order: query, query_pos, value, reference_points_cam,
// bev_mask, Wv, bv, Wo, bo, Wa, ba, Wout, bout, Hf, Wf
// ---------------------------------------------------------------------------
extern "C" void kernel_launch(void* const* d_in, const int* in_sizes, int n_in,
                              void* d_out, int out_size)
{
    const float* query     = (const float*)d_in[0];
    const float* query_pos = (const float*)d_in[1];
    const float* value     = (const float*)d_in[2];
    const float* refpts    = (const float*)d_in[3];
    const int*   bev_mask  = (const int*)  d_in[4];
    const float* Wv        = (const float*)d_in[5];
    const float* bv        = (const float*)d_in[6];
    const float* Wo        = (const float*)d_in[7];
    const float* bo        = (const float*)d_in[8];
    const float* Wa        = (const float*)d_in[9];
    const float* ba        = (const float*)d_in[10];
    const float* Wout      = (const float*)d_in[11];
    const float* bout      = (const float*)d_in[12];
    float* out = (float*)d_out;

    woutpack_kernel<<<(64 * C_) / 256, 256>>>(Wout);
    vproj_kernel<<<(S_ * M_) / TPB, 128>>>(value, Wv, bv);
    pairbuild_kernel<<<(S_ * H_ * M_ * CH) / 256, 256>>>();
    param_kernel<<<N_ / PQ, 96>>>(query, query_pos, Wo, bo, Wa, ba);
    bevformer_main_kernel<<<N_ / QPB, 128>>>(query, refpts, bev_mask, bout, out);
}